// round 14
// baseline (speedup 1.0000x reference)
#include <cuda_runtime.h>
#include <cstdint>

#define Bn 64
#define Tn 2048
#define Dn 512
#define Un 32
#define FULLM 0xffffffffu
typedef unsigned long long ull;

// ---------------- packed f32x2 ops ----------------
__device__ __forceinline__ ull fma2(ull a, ull b, ull c) {
    ull d;
    asm("fma.rn.f32x2 %0, %1, %2, %3;" : "=l"(d) : "l"(a), "l"(b), "l"(c));
    return d;
}
__device__ __forceinline__ ull add2(ull a, ull b) {
    ull d;
    asm("add.rn.f32x2 %0, %1, %2;" : "=l"(d) : "l"(a), "l"(b));
    return d;
}
__device__ __forceinline__ void unpack2(ull a, float& lo, float& hi) {
    asm("mov.b64 {%0, %1}, %2;" : "=f"(lo), "=f"(hi) : "l"(a));
}
__device__ __forceinline__ ull pack2(float lo, float hi) {
    ull d;
    asm("mov.b64 %0, {%1, %2};" : "=l"(d) : "f"(lo), "f"(hi));
    return d;
}
__device__ __forceinline__ void cp16(float* smem_ptr, const float* gptr) {
    unsigned saddr = (unsigned)__cvta_generic_to_shared(smem_ptr);
    asm volatile("cp.async.cg.shared.global [%0], [%1], 16;" :: "r"(saddr), "l"(gptr));
}

#define NCHUNK 32
#define NJOBS (NCHUNK * Bn)  // 2048 gemm chunk-jobs
#define NBLOCKS 456          // 152 SMs x occ3

// viterbi smem layout (byte offsets after 64KB bp)
#define ABUF 65536           // 2 x 32 floats                -> 256
#define PMAP 65792           // 32 chunks x 32 origins       -> 1024
#define ANCH 66816           // 32 ints                      -> 128
#define SFIN 66944           // 8
#define SMEM_BYTES 66952

// scratch: 16 MB logits + control block (flags | roles | counters), one memset
__device__ float g_logits[(size_t)Bn * Tn * Un];
// [0,2048) chunk flags (b*32+c); [2048,2304) sm role; [2304] vit ctr; [2305] job ctr
__device__ int g_ctrl[2048 + 256 + 2];

// ================= GEMM job: 64 rows (one 64-step chunk of one batch) ==========
__device__ void gemm_role(int c, int b, const float* __restrict__ x,
                          const float* __restrict__ W,
                          const float* __restrict__ bias, char* smem) {
    float* sx = (float*)smem;  // 2 x 64 x 128 floats (64KB)
    const int tid = threadIdx.x;
    const size_t row0 = (size_t)b * Tn + c * 64;

    {
        const float* gsrc = x + row0 * Dn;
#pragma unroll
        for (int q = 0; q < 16; q++) {
            int lin = tid + 128 * q;
            int rr = lin >> 5, cc = lin & 31;
            cp16(sx + rr * 128 + cc * 4, gsrc + (size_t)rr * Dn + cc * 4);
        }
        asm volatile("cp.async.commit_group;");
    }

    const int w = tid >> 5, u = tid & 31;
    const int wr0 = w * 16;

    ull acc[16];
#pragma unroll
    for (int r = 0; r < 16; r++) acc[r] = 0ull;

    for (int kt = 0; kt < 4; kt++) {
        if (kt < 3) {
            const float* gsrc = x + row0 * Dn + (kt + 1) * 128;
            float* sdst = sx + ((kt + 1) & 1) * 8192;
#pragma unroll
            for (int q = 0; q < 16; q++) {
                int lin = tid + 128 * q;
                int rr = lin >> 5, cc = lin & 31;
                cp16(sdst + rr * 128 + cc * 4, gsrc + (size_t)rr * Dn + cc * 4);
            }
            asm volatile("cp.async.commit_group;");
            asm volatile("cp.async.wait_group 1;");
        } else {
            asm volatile("cp.async.wait_group 0;");
        }
        __syncthreads();

        const float* xbuf = sx + (kt & 1) * 8192;
        const float* wg = W + (kt * 128) * Un + u;
        for (int k8 = 0; k8 < 128; k8 += 8) {
            float wv0 = __ldg(wg + (k8 + 0) * Un);
            float wv1 = __ldg(wg + (k8 + 1) * Un);
            float wv2 = __ldg(wg + (k8 + 2) * Un);
            float wv3 = __ldg(wg + (k8 + 3) * Un);
            float wv4 = __ldg(wg + (k8 + 4) * Un);
            float wv5 = __ldg(wg + (k8 + 5) * Un);
            float wv6 = __ldg(wg + (k8 + 6) * Un);
            float wv7 = __ldg(wg + (k8 + 7) * Un);
            ull wp0 = pack2(wv0, wv1), wp1 = pack2(wv2, wv3);
            ull wp2 = pack2(wv4, wv5), wp3 = pack2(wv6, wv7);
#pragma unroll
            for (int r = 0; r < 16; r++) {
                const float* xr = xbuf + (wr0 + r) * 128 + k8;
                ulonglong2 x0 = *(const ulonglong2*)(xr);
                ulonglong2 x1 = *(const ulonglong2*)(xr + 4);
                acc[r] = fma2(x0.x, wp0, acc[r]);
                acc[r] = fma2(x0.y, wp1, acc[r]);
                acc[r] = fma2(x1.x, wp2, acc[r]);
                acc[r] = fma2(x1.y, wp3, acc[r]);
            }
        }
        __syncthreads();
    }

    float bu = bias[u];
#pragma unroll
    for (int r = 0; r < 16; r++) {
        float lo, hi;
        unpack2(acc[r], lo, hi);
        g_logits[(row0 + wr0 + r) * Un + u] = lo + hi + bu;
    }
    __syncthreads();
    if (tid == 0) {
        __threadfence();
        atomicExch(&g_ctrl[b * NCHUNK + c], 1);
    }
}

// ================= Viterbi role: R10 vstep minus comp, pmap backtrack ==========
// tid: j = tid>>2 (target tag), sub = tid&3 (i-range sub*8..sub*8+7)
__device__ __forceinline__ float ldclamp(const float* lg, int t, int tmax, int j) {
    int ti = t <= tmax ? t : tmax;
    return lg[ti * Un + j];
}

__device__ __forceinline__ void vstep(int t, float lgt, const ull* tcp, float* abuf,
                                      unsigned char* bp, int j, int sub) {
    __syncthreads();  // previous step's abuf store visible
    const ulonglong2* ap = (const ulonglong2*)(abuf + ((t - 1) & 1) * 32 + sub * 8);
    ulonglong2 a0 = ap[0];
    ulonglong2 a1 = ap[1];
    ull s0 = add2(a0.x, tcp[0]);
    ull s1 = add2(a0.y, tcp[1]);
    ull s2 = add2(a1.x, tcp[2]);
    ull s3 = add2(a1.y, tcp[3]);
    float v0, v1, v2, v3, v4, v5, v6, v7;
    unpack2(s0, v0, v1);
    unpack2(s1, v2, v3);
    unpack2(s2, v4, v5);
    unpack2(s3, v6, v7);
    const int ib = sub * 8;
    // 8 -> 1, strict '>' so lower index wins ties (matches jnp.argmax)
    bool gA = v1 > v0; float m01 = fmaxf(v0, v1); int i01 = gA ? ib + 1 : ib;
    bool gB = v3 > v2; float m23 = fmaxf(v2, v3); int i23 = gB ? ib + 3 : ib + 2;
    bool gC = v5 > v4; float m45 = fmaxf(v4, v5); int i45 = gC ? ib + 5 : ib + 4;
    bool gD = v7 > v6; float m67 = fmaxf(v6, v7); int i67 = gD ? ib + 7 : ib + 6;
    bool gE = m23 > m01; float mA = fmaxf(m01, m23); int iA = gE ? i23 : i01;
    bool gF = m67 > m45; float mB = fmaxf(m45, m67); int iB = gF ? i67 : i45;
    bool gG = mB > mA; float val = fmaxf(mA, mB); int idx = gG ? iB : iA;
    // quad merge (sub ranges ordered by sub -> first-occurrence preserved)
#pragma unroll
    for (int d = 1; d <= 2; d <<= 1) {
        float pv = __shfl_xor_sync(FULLM, val, d);
        int pi = __shfl_xor_sync(FULLM, idx, d);
        bool take = (pv > val) || (pv == val && pi < idx);
        val = take ? pv : val;
        idx = take ? pi : idx;
    }
    // parallel stores on different subs; no comp chain
    if (sub == 0) abuf[(t & 1) * 32 + j] = val + lgt;
    if (sub == 1) bp[t * 32 + j] = (unsigned char)idx;
}

__device__ __forceinline__ void waitchunk(int b, int c) {
    if (c > NCHUNK - 1) c = NCHUNK - 1;
    volatile int* f = &g_ctrl[b * NCHUNK + c];
    while (*f == 0) {}
    __threadfence();  // acquire
}

__device__ void viterbi_role(int b, const float* __restrict__ trans,
                             float* __restrict__ out, int write_pred, int write_score,
                             long long score_off, const int* __restrict__ nwords,
                             char* sm8) {
    unsigned char* bp = (unsigned char*)sm8;        // [0, 65536)
    float* abuf = (float*)(sm8 + ABUF);
    unsigned char* pmap = (unsigned char*)(sm8 + PMAP);
    int* anch = (int*)(sm8 + ANCH);
    int* sfin = (int*)(sm8 + SFIN);

    const int tid = threadIdx.x;
    const int j = tid >> 2;
    const int sub = tid & 3;
    int len = nwords[b];
    if (len < 1) len = 1;
    if (len > Tn) len = Tn;
    const int tmax = len - 1;

    const float* lg = g_logits + (size_t)b * Tn * Un;

    ull tcp[4];
#pragma unroll
    for (int p = 0; p < 4; p++)
        tcp[p] = pack2(trans[(sub * 8 + 2 * p) * Un + j],
                       trans[(sub * 8 + 2 * p + 1) * Un + j]);

    waitchunk(b, 0);
    if (tid < 32) abuf[tid] = lg[tid];  // alpha0
    __syncthreads();

    // 4-deep rotating logit prefetch
    float pl0 = ldclamp(lg, 1, tmax, j);
    float pl1 = ldclamp(lg, 2, tmax, j);
    float pl2 = ldclamp(lg, 3, tmax, j);
    float pl3 = ldclamp(lg, 4, tmax, j);

    int t = 1;
    for (; t + 3 <= tmax; t += 4) {
        if ((t & 63) == 1) waitchunk(b, (t >> 6) + 1);  // next chunk (prefetch reach)
        float n0 = ldclamp(lg, t + 4, tmax, j);
        float n1 = ldclamp(lg, t + 5, tmax, j);
        float n2 = ldclamp(lg, t + 6, tmax, j);
        float n3 = ldclamp(lg, t + 7, tmax, j);
        vstep(t, pl0, tcp, abuf, bp, j, sub);
        vstep(t + 1, pl1, tcp, abuf, bp, j, sub);
        vstep(t + 2, pl2, tcp, abuf, bp, j, sub);
        vstep(t + 3, pl3, tcp, abuf, bp, j, sub);
        pl0 = n0; pl1 = n1; pl2 = n2; pl3 = n3;
    }
    for (; t <= tmax; t++) {
        if ((t & 63) == 1) waitchunk(b, (t >> 6) + 1);
        vstep(t, pl0, tcp, abuf, bp, j, sub);
        pl0 = pl1; pl1 = pl2; pl2 = pl3;
    }
    __syncthreads();

    const int fslot = (tmax & 1) * 32;
    if (tid < 32) {
        float bv = abuf[fslot + tid];
        int bi = tid;
#pragma unroll
        for (int off = 16; off >= 1; off >>= 1) {
            float ov = __shfl_xor_sync(FULLM, bv, off);
            int oi = __shfl_xor_sync(FULLM, bi, off);
            if (ov > bv || (ov == bv && oi < bi)) { bv = ov; bi = oi; }
        }
        if (tid == 0) {
            sfin[0] = bi;
            if (write_score) out[score_off + b] = bv;
        }
    }
    __syncthreads();
    const int last_tag = sfin[0];

    if (write_pred) {
        // per-chunk backward maps: pmap[c][e] = tag@(c*64) given tag e@min((c+1)*64,tmax)
        int tg[8], clo[8], thi[8];
#pragma unroll
        for (int r = 0; r < 8; r++) {
            int p = tid + 128 * r;
            int c = p >> 5;
            tg[r] = p & 31;
            int th = (c + 1) << 6;
            if (th > tmax) th = tmax;
            clo[r] = c << 6;
            thi[r] = th;
        }
        for (int s = 0; s < 64; s++) {
#pragma unroll
            for (int r = 0; r < 8; r++) {
                int tt = thi[r] - s;
                if (tt > clo[r]) tg[r] = bp[tt * 32 + tg[r]];
            }
        }
#pragma unroll
        for (int r = 0; r < 8; r++) {
            int p = tid + 128 * r;
            pmap[(p >> 5) * 32 + (p & 31)] = (unsigned char)tg[r];
        }
        __syncthreads();

        const int cmax = tmax >> 6;
        if (tid == 0) {
            int a = last_tag;
            for (int c = cmax; c >= 0; --c) {
                a = pmap[c * 32 + a];
                anch[c] = a;  // tag @ c*64
            }
        }
        for (int tt = tmax + tid; tt < Tn; tt += 128)
            out[(size_t)b * Tn + tt] = (float)last_tag;
        __syncthreads();

        // parallel per-chunk backtrack (thread c handles t in (c*64, t_hi])
        if (tid <= cmax) {
            int thi2 = (tid == cmax) ? tmax : ((tid + 1) << 6);
            int tg2 = (tid == cmax) ? last_tag : anch[tid + 1];
            for (int tt = thi2; tt > (tid << 6); --tt) {
                tg2 = bp[tt * 32 + tg2];
                out[(size_t)b * Tn + tt - 1] = (float)tg2;
            }
        }
    }
}

// ================= persistent fused kernel with SM-role isolation ==============
__global__ __launch_bounds__(128, 3) void crf_fused(const float* __restrict__ x,
                                                    const int* __restrict__ nwords,
                                                    const float* __restrict__ W,
                                                    const float* __restrict__ trans,
                                                    const float* __restrict__ bias,
                                                    float* __restrict__ out,
                                                    int write_pred, int write_score,
                                                    long long score_off) {
    extern __shared__ char smem[];
    __shared__ int s_role;
    __shared__ int s_batch;
    __shared__ int s_job;

    const int tid = threadIdx.x;
    if (tid == 0) {
        unsigned smid;
        asm("mov.u32 %0, %%smid;" : "=r"(smid));
        int* rp = &g_ctrl[2048 + (smid & 255)];
        int r = atomicCAS(rp, 0, 1);
        if (r == 0) {
            int vb = atomicAdd(&g_ctrl[2304], 1);
            if (vb < Bn) {
                s_batch = vb;
                atomicExch(rp, 3);
                s_role = 1;
            } else {
                atomicExch(rp, 2);
                s_role = 2;
            }
        } else {
            volatile int* vp = rp;
            int v;
            while ((v = *vp) < 2) {}
            s_role = (v == 3) ? 0 : 2;
        }
    }
    __syncthreads();
    const int role = s_role;
    if (role == 0) return;

    if (role == 1) {
        viterbi_role(s_batch, trans, out, write_pred, write_score, score_off,
                     nwords, smem);
        return;
    }
    while (true) {
        if (tid == 0) s_job = atomicAdd(&g_ctrl[2305], 1);
        __syncthreads();
        int job = s_job;
        if (job >= NJOBS) break;
        gemm_role(job >> 6, job & 63, x, W, bias, smem);
        __syncthreads();
    }
}

// ---------------- launch ----------------
extern "C" void kernel_launch(void* const* d_in, const int* in_sizes, int n_in,
                              void* d_out, int out_size) {
    const float* x = (const float*)d_in[0];
    const int* nwords = (const int*)d_in[1];
    const float* W = (const float*)d_in[2];
    const float* trans = (const float*)d_in[3];
    const float* bias = (const float*)d_in[4];
    float* out = (float*)d_out;

    const int BT = Bn * Tn;
    int write_pred = 1, write_score = 0;
    long long score_off = BT;
    if (out_size >= BT + Bn) {
        write_score = 1;
    } else if (out_size == Bn) {
        write_pred = 0;
        write_score = 1;
        score_off = 0;
    }

    static int* ctrl_ptr = nullptr;
    if (!ctrl_ptr) cudaGetSymbolAddress((void**)&ctrl_ptr, g_ctrl);

    cudaFuncSetAttribute(crf_fused, cudaFuncAttributeMaxDynamicSharedMemorySize, SMEM_BYTES);

    cudaMemsetAsync(ctrl_ptr, 0, (2048 + 256 + 2) * sizeof(int));
    crf_fused<<<NBLOCKS, 128, SMEM_BYTES>>>(x, nwords, W, trans, bias, out,
                                            write_pred, write_score, score_off);
}

// round 15
// speedup vs baseline: 1.0307x; 1.0307x over previous
#include <cuda_runtime.h>
#include <cstdint>

#define Bn 64
#define Tn 2048
#define Dn 512
#define Un 32
#define FULLM 0xffffffffu
typedef unsigned long long ull;

// ---------------- packed f32x2 ops ----------------
__device__ __forceinline__ ull fma2(ull a, ull b, ull c) {
    ull d;
    asm("fma.rn.f32x2 %0, %1, %2, %3;" : "=l"(d) : "l"(a), "l"(b), "l"(c));
    return d;
}
__device__ __forceinline__ ull add2(ull a, ull b) {
    ull d;
    asm("add.rn.f32x2 %0, %1, %2;" : "=l"(d) : "l"(a), "l"(b));
    return d;
}
__device__ __forceinline__ void unpack2(ull a, float& lo, float& hi) {
    asm("mov.b64 {%0, %1}, %2;" : "=f"(lo), "=f"(hi) : "l"(a));
}
__device__ __forceinline__ ull pack2(float lo, float hi) {
    ull d;
    asm("mov.b64 %0, {%1, %2};" : "=l"(d) : "f"(lo), "f"(hi));
    return d;
}
__device__ __forceinline__ void cp16(float* smem_ptr, const float* gptr) {
    unsigned saddr = (unsigned)__cvta_generic_to_shared(smem_ptr);
    asm volatile("cp.async.cg.shared.global [%0], [%1], 16;" :: "r"(saddr), "l"(gptr));
}

#define NCHUNK 32
#define NJOBS (NCHUNK * Bn)  // 2048 gemm chunk-jobs
#define NBLOCKS 456          // 152 SMs x occ3

// viterbi smem layout (byte offsets after 64KB bp)
#define ABUF 65536           // 2 x 32 floats               -> 256
#define SVAL 65792           // 2 par x 32 j x 16B prevals  -> 1024
#define SIDX 66816           // 2 par x 32 j x 4B idx bytes -> 256
#define PMAP 67072           // 32 chunks x 32 origins      -> 1024
#define ANCH 68096           // 32 ints                     -> 128
#define SFIN 68224           // 8
#define SMEM_BYTES 68232

// scratch: 16 MB logits + control block (flags | roles | counters), one memset
__device__ float g_logits[(size_t)Bn * Tn * Un];
// [0,2048) chunk flags (b*32+c); [2048,2304) sm role; [2304] vit ctr; [2305] job ctr
__device__ int g_ctrl[2048 + 256 + 2];

// ================= GEMM job: 64 rows (one 64-step chunk of one batch) ==========
__device__ void gemm_role(int c, int b, const float* __restrict__ x,
                          const float* __restrict__ W,
                          const float* __restrict__ bias, char* smem) {
    float* sx = (float*)smem;  // 2 x 64 x 128 floats (64KB)
    const int tid = threadIdx.x;
    const size_t row0 = (size_t)b * Tn + c * 64;

    {
        const float* gsrc = x + row0 * Dn;
#pragma unroll
        for (int q = 0; q < 16; q++) {
            int lin = tid + 128 * q;
            int rr = lin >> 5, cc = lin & 31;
            cp16(sx + rr * 128 + cc * 4, gsrc + (size_t)rr * Dn + cc * 4);
        }
        asm volatile("cp.async.commit_group;");
    }

    const int w = tid >> 5, u = tid & 31;
    const int wr0 = w * 16;

    ull acc[16];
#pragma unroll
    for (int r = 0; r < 16; r++) acc[r] = 0ull;

    for (int kt = 0; kt < 4; kt++) {
        if (kt < 3) {
            const float* gsrc = x + row0 * Dn + (kt + 1) * 128;
            float* sdst = sx + ((kt + 1) & 1) * 8192;
#pragma unroll
            for (int q = 0; q < 16; q++) {
                int lin = tid + 128 * q;
                int rr = lin >> 5, cc = lin & 31;
                cp16(sdst + rr * 128 + cc * 4, gsrc + (size_t)rr * Dn + cc * 4);
            }
            asm volatile("cp.async.commit_group;");
            asm volatile("cp.async.wait_group 1;");
        } else {
            asm volatile("cp.async.wait_group 0;");
        }
        __syncthreads();

        const float* xbuf = sx + (kt & 1) * 8192;
        const float* wg = W + (kt * 128) * Un + u;
        for (int k8 = 0; k8 < 128; k8 += 8) {
            float wv0 = __ldg(wg + (k8 + 0) * Un);
            float wv1 = __ldg(wg + (k8 + 1) * Un);
            float wv2 = __ldg(wg + (k8 + 2) * Un);
            float wv3 = __ldg(wg + (k8 + 3) * Un);
            float wv4 = __ldg(wg + (k8 + 4) * Un);
            float wv5 = __ldg(wg + (k8 + 5) * Un);
            float wv6 = __ldg(wg + (k8 + 6) * Un);
            float wv7 = __ldg(wg + (k8 + 7) * Un);
            ull wp0 = pack2(wv0, wv1), wp1 = pack2(wv2, wv3);
            ull wp2 = pack2(wv4, wv5), wp3 = pack2(wv6, wv7);
#pragma unroll
            for (int r = 0; r < 16; r++) {
                const float* xr = xbuf + (wr0 + r) * 128 + k8;
                ulonglong2 x0 = *(const ulonglong2*)(xr);
                ulonglong2 x1 = *(const ulonglong2*)(xr + 4);
                acc[r] = fma2(x0.x, wp0, acc[r]);
                acc[r] = fma2(x0.y, wp1, acc[r]);
                acc[r] = fma2(x1.x, wp2, acc[r]);
                acc[r] = fma2(x1.y, wp3, acc[r]);
            }
        }
        __syncthreads();
    }

    float bu = bias[u];
#pragma unroll
    for (int r = 0; r < 16; r++) {
        float lo, hi;
        unpack2(acc[r], lo, hi);
        g_logits[(row0 + wr0 + r) * Un + u] = lo + hi + bu;
    }
    __syncthreads();
    if (tid == 0) {
        __threadfence();
        atomicExch(&g_ctrl[b * NCHUNK + c], 1);
    }
}

// ================= Viterbi: value-only chain, deferred bp resolution ===========
// tid: j = tid>>2 (target tag), sub = tid&3 (i-range sub*8..sub*8+7)
__device__ __forceinline__ float ldclamp(const float* lg, int t, int tmax, int j) {
    int ti = t <= tmax ? t : tmax;
    return lg[ti * Un + j];
}

__device__ __forceinline__ void vstep(int t, float lgt, const ull* tcp, char* sm8,
                                      unsigned char* bp, int j, int sub) {
    __syncthreads();  // prior step's stores visible
    const int par = (t - 1) & 1;
    const int cur = t & 1;
    const float* ab = (const float*)(sm8 + ABUF) + par * 32;
    const ulonglong2* ap = (const ulonglong2*)(ab + sub * 8);
    ulonglong2 a0 = ap[0];
    ulonglong2 a1 = ap[1];
    ull s0 = add2(a0.x, tcp[0]);
    ull s1 = add2(a0.y, tcp[1]);
    ull s2 = add2(a1.x, tcp[2]);
    ull s3 = add2(a1.y, tcp[3]);
    float v0, v1, v2, v3, v4, v5, v6, v7;
    unpack2(s0, v0, v1);
    unpack2(s1, v2, v3);
    unpack2(s2, v4, v5);
    unpack2(s3, v6, v7);
    // value chain: pure fmax tree, no selects
    float m01 = fmaxf(v0, v1), m23 = fmaxf(v2, v3);
    float m45 = fmaxf(v4, v5), m67 = fmaxf(v6, v7);
    float n0 = fmaxf(m01, m23), n1 = fmaxf(m45, m67);
    float subval = fmaxf(n0, n1);
    // value-only quad merge (the only cross-lane chain)
    float g1 = fmaxf(subval, __shfl_xor_sync(FULLM, subval, 1));
    float gv = fmaxf(g1, __shfl_xor_sync(FULLM, g1, 2));
    // sub-local argmax: off the value chain (runs beside the shfl merge).
    // strict '>' -> lowest index wins ties (matches jnp.argmax)
    bool gA = v1 > v0; int i01 = gA ? 1 : 0;
    bool gB = v3 > v2; int i23 = gB ? 3 : 2;
    bool gC = v5 > v4; int i45 = gC ? 5 : 4;
    bool gD = v7 > v6; int i67 = gD ? 7 : 6;
    bool gE = m23 > m01; int iA = gE ? i23 : i01;
    bool gF = m67 > m45; int iB = gF ? i67 : i45;
    bool gG = n1 > n0; int sidx = sub * 8 + (gG ? iB : iA);
    // shadow (sub3): resolve bp[t-1] from last step's (preval, idx) partials.
    // first-max-sub via strict '>' + sub-local lowest idx = global first occurrence.
    if (sub == 3 && t >= 2) {
        float4 pv = *(const float4*)(sm8 + SVAL + par * 512 + j * 16);
        unsigned iw = *(const unsigned*)(sm8 + SIDX + par * 128 + j * 4);
        float bvv = pv.x; unsigned bx = iw & 255u;
        if (pv.y > bvv) { bvv = pv.y; bx = (iw >> 8) & 255u; }
        if (pv.z > bvv) { bvv = pv.z; bx = (iw >> 16) & 255u; }
        if (pv.w > bvv) { bvv = pv.w; bx = (iw >> 24) & 255u; }
        bp[(t - 1) * 32 + j] = (unsigned char)bx;
    }
    // publish
    if (sub == 0) *((float*)(sm8 + ABUF) + cur * 32 + j) = gv + lgt;
    *(float*)(sm8 + SVAL + cur * 512 + j * 16 + sub * 4) = subval;
    *(unsigned char*)(sm8 + SIDX + cur * 128 + j * 4 + sub) = (unsigned char)sidx;
}

__device__ __forceinline__ void waitchunk(int b, int c) {
    if (c > NCHUNK - 1) c = NCHUNK - 1;
    volatile int* f = &g_ctrl[b * NCHUNK + c];
    while (*f == 0) {}
    __threadfence();  // acquire
}

__device__ void viterbi_role(int b, const float* __restrict__ trans,
                             float* __restrict__ out, int write_pred, int write_score,
                             long long score_off, const int* __restrict__ nwords,
                             char* sm8) {
    unsigned char* bp = (unsigned char*)sm8;  // [0, 65536)
    unsigned char* pmap = (unsigned char*)(sm8 + PMAP);
    int* anch = (int*)(sm8 + ANCH);
    int* sfin = (int*)(sm8 + SFIN);

    const int tid = threadIdx.x;
    const int j = tid >> 2;
    const int sub = tid & 3;
    int len = nwords[b];
    if (len < 1) len = 1;
    if (len > Tn) len = Tn;
    const int tmax = len - 1;

    const float* lg = g_logits + (size_t)b * Tn * Un;

    ull tcp[4];
#pragma unroll
    for (int p = 0; p < 4; p++)
        tcp[p] = pack2(trans[(sub * 8 + 2 * p) * Un + j],
                       trans[(sub * 8 + 2 * p + 1) * Un + j]);

    waitchunk(b, 0);
    if (tid < 32) *((float*)(sm8 + ABUF) + tid) = lg[tid];  // alpha0, parity 0
    __syncthreads();

    // 8-deep rotating logit prefetch
    float pl[8];
#pragma unroll
    for (int q = 0; q < 8; q++) pl[q] = ldclamp(lg, 1 + q, tmax, j);

    int t = 1;
    for (; t + 3 <= tmax; t += 4) {
        if ((t & 63) == 1) waitchunk(b, (t >> 6) + 1);  // covers prefetch reach
        float n0 = ldclamp(lg, t + 8, tmax, j);
        float n1 = ldclamp(lg, t + 9, tmax, j);
        float n2 = ldclamp(lg, t + 10, tmax, j);
        float n3 = ldclamp(lg, t + 11, tmax, j);
        vstep(t, pl[0], tcp, sm8, bp, j, sub);
        vstep(t + 1, pl[1], tcp, sm8, bp, j, sub);
        vstep(t + 2, pl[2], tcp, sm8, bp, j, sub);
        vstep(t + 3, pl[3], tcp, sm8, bp, j, sub);
        pl[0] = pl[4]; pl[1] = pl[5]; pl[2] = pl[6]; pl[3] = pl[7];
        pl[4] = n0; pl[5] = n1; pl[6] = n2; pl[7] = n3;
    }
    for (; t <= tmax; t++) {
        if ((t & 63) == 1) waitchunk(b, (t >> 6) + 1);
        vstep(t, pl[0], tcp, sm8, bp, j, sub);
#pragma unroll
        for (int q = 0; q < 7; q++) pl[q] = pl[q + 1];
    }
    __syncthreads();

    // epilogue: bp[tmax] resolution + final warp argmax
    const int fpar = tmax & 1;
    if (tid < 32) {
        if (tmax >= 1) {
            float4 pv = *(const float4*)(sm8 + SVAL + fpar * 512 + tid * 16);
            unsigned iw = *(const unsigned*)(sm8 + SIDX + fpar * 128 + tid * 4);
            float bvv = pv.x; unsigned bx = iw & 255u;
            if (pv.y > bvv) { bvv = pv.y; bx = (iw >> 8) & 255u; }
            if (pv.z > bvv) { bvv = pv.z; bx = (iw >> 16) & 255u; }
            if (pv.w > bvv) { bvv = pv.w; bx = (iw >> 24) & 255u; }
            bp[tmax * 32 + tid] = (unsigned char)bx;
        }
        float bv = *((const float*)(sm8 + ABUF) + fpar * 32 + tid);
        int bi = tid;
#pragma unroll
        for (int off = 16; off >= 1; off >>= 1) {
            float ov = __shfl_xor_sync(FULLM, bv, off);
            int oi = __shfl_xor_sync(FULLM, bi, off);
            if (ov > bv || (ov == bv && oi < bi)) { bv = ov; bi = oi; }
        }
        if (tid == 0) {
            sfin[0] = bi;
            if (write_score) out[score_off + b] = bv;
        }
    }
    __syncthreads();
    const int last_tag = sfin[0];

    if (write_pred) {
        // per-chunk backward maps: pmap[c][e] = tag@(c*64) given tag e@min((c+1)*64,tmax)
        int tg[8], clo[8], thi[8];
#pragma unroll
        for (int r = 0; r < 8; r++) {
            int p = tid + 128 * r;
            int c = p >> 5;
            tg[r] = p & 31;
            int th = (c + 1) << 6;
            if (th > tmax) th = tmax;
            clo[r] = c << 6;
            thi[r] = th;
        }
        for (int s = 0; s < 64; s++) {
#pragma unroll
            for (int r = 0; r < 8; r++) {
                int tt = thi[r] - s;
                if (tt > clo[r]) tg[r] = bp[tt * 32 + tg[r]];
            }
        }
#pragma unroll
        for (int r = 0; r < 8; r++) {
            int p = tid + 128 * r;
            pmap[(p >> 5) * 32 + (p & 31)] = (unsigned char)tg[r];
        }
        __syncthreads();

        const int cmax = tmax >> 6;
        if (tid == 0) {
            int a = last_tag;
            for (int c = cmax; c >= 0; --c) {
                a = pmap[c * 32 + a];
                anch[c] = a;  // tag @ c*64
            }
        }
        for (int tt = tmax + tid; tt < Tn; tt += 128)
            out[(size_t)b * Tn + tt] = (float)last_tag;
        __syncthreads();

        // parallel per-chunk backtrack (thread c handles t in (c*64, t_hi])
        if (tid <= cmax) {
            int thi2 = (tid == cmax) ? tmax : ((tid + 1) << 6);
            int tg2 = (tid == cmax) ? last_tag : anch[tid + 1];
            for (int tt = thi2; tt > (tid << 6); --tt) {
                tg2 = bp[tt * 32 + tg2];
                out[(size_t)b * Tn + tt - 1] = (float)tg2;
            }
        }
    }
}

// ================= persistent fused kernel with SM-role isolation ==============
__global__ __launch_bounds__(128, 3) void crf_fused(const float* __restrict__ x,
                                                    const int* __restrict__ nwords,
                                                    const float* __restrict__ W,
                                                    const float* __restrict__ trans,
                                                    const float* __restrict__ bias,
                                                    float* __restrict__ out,
                                                    int write_pred, int write_score,
                                                    long long score_off) {
    extern __shared__ char smem[];
    __shared__ int s_role;
    __shared__ int s_batch;
    __shared__ int s_job;

    const int tid = threadIdx.x;
    if (tid == 0) {
        unsigned smid;
        asm("mov.u32 %0, %%smid;" : "=r"(smid));
        int* rp = &g_ctrl[2048 + (smid & 255)];
        int r = atomicCAS(rp, 0, 1);
        if (r == 0) {
            int vb = atomicAdd(&g_ctrl[2304], 1);
            if (vb < Bn) {
                s_batch = vb;
                atomicExch(rp, 3);
                s_role = 1;
            } else {
                atomicExch(rp, 2);
                s_role = 2;
            }
        } else {
            volatile int* vp = rp;
            int v;
            while ((v = *vp) < 2) {}
            s_role = (v == 3) ? 0 : 2;
        }
    }
    __syncthreads();
    const int role = s_role;
    if (role == 0) return;

    if (role == 1) {
        viterbi_role(s_batch, trans, out, write_pred, write_score, score_off,
                     nwords, smem);
        return;
    }
    while (true) {
        if (tid == 0) s_job = atomicAdd(&g_ctrl[2305], 1);
        __syncthreads();
        int job = s_job;
        if (job >= NJOBS) break;
        gemm_role(job >> 6, job & 63, x, W, bias, smem);
        __syncthreads();
    }
}

// ---------------- launch ----------------
extern "C" void kernel_launch(void* const* d_in, const int* in_sizes, int n_in,
                              void* d_out, int out_size) {
    const float* x = (const float*)d_in[0];
    const int* nwords = (const int*)d_in[1];
    const float* W = (const float*)d_in[2];
    const float* trans = (const float*)d_in[3];
    const float* bias = (const float*)d_in[4];
    float* out = (float*)d_out;

    const int BT = Bn * Tn;
    int write_pred = 1, write_score = 0;
    long long score_off = BT;
    if (out_size >= BT + Bn) {
        write_score = 1;
    } else if (out_size == Bn) {
        write_pred = 0;
        write_score = 1;
        score_off = 0;
    }

    static int* ctrl_ptr = nullptr;
    if (!ctrl_ptr) cudaGetSymbolAddress((void**)&ctrl_ptr, g_ctrl);

    cudaFuncSetAttribute(crf_fused, cudaFuncAttributeMaxDynamicSharedMemorySize, SMEM_BYTES);

    cudaMemsetAsync(ctrl_ptr, 0, (2048 + 256 + 2) * sizeof(int));
    crf_fused<<<NBLOCKS, 128, SMEM_BYTES>>>(x, nwords, W, trans, bias, out,
                                            write_pred, write_score, score_off);
}

// round 16
// speedup vs baseline: 1.1492x; 1.1150x over previous
#include <cuda_runtime.h>
#include <cstdint>

#define Bn 64
#define Tn 2048
#define Dn 512
#define Un 32
#define FULLM 0xffffffffu
typedef unsigned long long ull;

// ---------------- packed f32x2 ops ----------------
__device__ __forceinline__ ull fma2(ull a, ull b, ull c) {
    ull d;
    asm("fma.rn.f32x2 %0, %1, %2, %3;" : "=l"(d) : "l"(a), "l"(b), "l"(c));
    return d;
}
__device__ __forceinline__ ull add2(ull a, ull b) {
    ull d;
    asm("add.rn.f32x2 %0, %1, %2;" : "=l"(d) : "l"(a), "l"(b));
    return d;
}
__device__ __forceinline__ void unpack2(ull a, float& lo, float& hi) {
    asm("mov.b64 {%0, %1}, %2;" : "=f"(lo), "=f"(hi) : "l"(a));
}
__device__ __forceinline__ ull pack2(float lo, float hi) {
    ull d;
    asm("mov.b64 %0, {%1, %2};" : "=l"(d) : "f"(lo), "f"(hi));
    return d;
}
__device__ __forceinline__ void cp16(float* smem_ptr, const float* gptr) {
    unsigned saddr = (unsigned)__cvta_generic_to_shared(smem_ptr);
    asm volatile("cp.async.cg.shared.global [%0], [%1], 16;" :: "r"(saddr), "l"(gptr));
}

#define NCHUNK 32
#define NJOBS (NCHUNK * Bn)   // 2048 gemm chunk-jobs
#define NBLOCKS 456           // 152 SMs x occ3
#define NVIT 16               // viterbi blocks (4 batches each)

// uniform dynamic smem: viterbi uses [0,6144); gemm uses [0,65536)
#define VWSTRIDE 1536         // per-warp viterbi region: abuf 256 | pmap 1024 | anch 128
#define SMEM_BYTES 72704

// scratch: 16 MB logits + 4 MB backpointers + control block
__device__ float g_logits[(size_t)Bn * Tn * Un];
__device__ unsigned char g_bp[(size_t)Bn * Tn * 32];
// [0,2048) chunk flags (b*32+c); [2048,2304) sm role; [2304] vit ctr; [2305] job ctr
__device__ int g_ctrl[2048 + 256 + 2];

// ================= GEMM job: 64 rows (one 64-step chunk of one batch) ==========
__device__ void gemm_role(int c, int b, const float* __restrict__ x,
                          const float* __restrict__ W,
                          const float* __restrict__ bias, char* smem) {
    float* sx = (float*)smem;  // 2 x 64 x 128 floats (64KB)
    const int tid = threadIdx.x;
    const size_t row0 = (size_t)b * Tn + c * 64;

    {
        const float* gsrc = x + row0 * Dn;
#pragma unroll
        for (int q = 0; q < 16; q++) {
            int lin = tid + 128 * q;
            int rr = lin >> 5, cc = lin & 31;
            cp16(sx + rr * 128 + cc * 4, gsrc + (size_t)rr * Dn + cc * 4);
        }
        asm volatile("cp.async.commit_group;");
    }

    const int w = tid >> 5, u = tid & 31;
    const int wr0 = w * 16;

    ull acc[16];
#pragma unroll
    for (int r = 0; r < 16; r++) acc[r] = 0ull;

    for (int kt = 0; kt < 4; kt++) {
        if (kt < 3) {
            const float* gsrc = x + row0 * Dn + (kt + 1) * 128;
            float* sdst = sx + ((kt + 1) & 1) * 8192;
#pragma unroll
            for (int q = 0; q < 16; q++) {
                int lin = tid + 128 * q;
                int rr = lin >> 5, cc = lin & 31;
                cp16(sdst + rr * 128 + cc * 4, gsrc + (size_t)rr * Dn + cc * 4);
            }
            asm volatile("cp.async.commit_group;");
            asm volatile("cp.async.wait_group 1;");
        } else {
            asm volatile("cp.async.wait_group 0;");
        }
        __syncthreads();

        const float* xbuf = sx + (kt & 1) * 8192;
        const float* wg = W + (kt * 128) * Un + u;
        for (int k8 = 0; k8 < 128; k8 += 8) {
            float wv0 = __ldg(wg + (k8 + 0) * Un);
            float wv1 = __ldg(wg + (k8 + 1) * Un);
            float wv2 = __ldg(wg + (k8 + 2) * Un);
            float wv3 = __ldg(wg + (k8 + 3) * Un);
            float wv4 = __ldg(wg + (k8 + 4) * Un);
            float wv5 = __ldg(wg + (k8 + 5) * Un);
            float wv6 = __ldg(wg + (k8 + 6) * Un);
            float wv7 = __ldg(wg + (k8 + 7) * Un);
            ull wp0 = pack2(wv0, wv1), wp1 = pack2(wv2, wv3);
            ull wp2 = pack2(wv4, wv5), wp3 = pack2(wv6, wv7);
#pragma unroll
            for (int r = 0; r < 16; r++) {
                const float* xr = xbuf + (wr0 + r) * 128 + k8;
                ulonglong2 x0 = *(const ulonglong2*)(xr);
                ulonglong2 x1 = *(const ulonglong2*)(xr + 4);
                acc[r] = fma2(x0.x, wp0, acc[r]);
                acc[r] = fma2(x0.y, wp1, acc[r]);
                acc[r] = fma2(x1.x, wp2, acc[r]);
                acc[r] = fma2(x1.y, wp3, acc[r]);
            }
        }
        __syncthreads();
    }

    float bu = bias[u];
#pragma unroll
    for (int r = 0; r < 16; r++) {
        float lo, hi;
        unpack2(acc[r], lo, hi);
        g_logits[(row0 + wr0 + r) * Un + u] = lo + hi + bu;
    }
    __syncthreads();
    if (tid == 0) {
        __threadfence();
        atomicExch(&g_ctrl[b * NCHUNK + c], 1);
    }
}

// ================= Viterbi: ONE WARP per batch, no block barriers ==============
__device__ __forceinline__ float ldclamp(const float* lg, int t, int tmax, int j) {
    int ti = t <= tmax ? t : tmax;
    return __ldg(lg + ti * Un + j);
}

__device__ __forceinline__ float vstep32(int t, float lgt, const ull* tcp,
                                         float* abuf, unsigned char* gbp, int j) {
    __syncwarp();  // prior step's abuf stores visible warp-wide
    const ulonglong2* ap = (const ulonglong2*)(abuf + ((t - 1) & 1) * 32);
    float qv[8];
    int qi[8];
#pragma unroll
    for (int q = 0; q < 8; q++) {
        ulonglong2 a = ap[q];  // broadcast LDS.128
        ull s0 = add2(a.x, tcp[2 * q]);
        ull s1 = add2(a.y, tcp[2 * q + 1]);
        float v0, v1, v2, v3;
        unpack2(s0, v0, v1);
        unpack2(s1, v2, v3);
        // strict '>' so lower index wins ties (matches jnp.argmax)
        bool g0 = v1 > v0; float m0 = fmaxf(v0, v1); int i0 = g0 ? 4 * q + 1 : 4 * q;
        bool g1 = v3 > v2; float m1 = fmaxf(v2, v3); int i1 = g1 ? 4 * q + 3 : 4 * q + 2;
        bool gc = m1 > m0;
        qv[q] = fmaxf(m0, m1);
        qi[q] = gc ? i1 : i0;
    }
#pragma unroll
    for (int s = 1; s < 8; s <<= 1) {
#pragma unroll
        for (int i = 0; i < 8; i += (s << 1)) {
            bool g = qv[i + s] > qv[i];
            qv[i] = fmaxf(qv[i], qv[i + s]);
            qi[i] = g ? qi[i + s] : qi[i];
        }
    }
    float na = qv[0] + lgt;
    abuf[(t & 1) * 32 + j] = na;             // STS.32
    gbp[t * 32 + j] = (unsigned char)qi[0];  // STG.8, fire-and-forget
    return na;
}

__device__ __forceinline__ void waitchunk(int b, int c) {
    if (c > NCHUNK - 1) c = NCHUNK - 1;
    volatile int* f = &g_ctrl[b * NCHUNK + c];
    while (*f == 0) {}
    __threadfence();  // acquire
}

__device__ void viterbi_warp(int b, const float* __restrict__ trans,
                             float* __restrict__ out, int write_pred, int write_score,
                             long long score_off, const int* __restrict__ nwords,
                             char* wsm) {
    float* abuf = (float*)wsm;                           // 256B (2 x 32)
    unsigned char* pmap = (unsigned char*)(wsm + 256);   // 1024B
    int* anch = (int*)(wsm + 256 + 1024);                // 128B

    const int j = threadIdx.x & 31;
    int len = nwords[b];
    if (len < 1) len = 1;
    if (len > Tn) len = Tn;
    const int tmax = len - 1;

    const float* lg = g_logits + (size_t)b * Tn * Un;
    unsigned char* gbp = g_bp + (size_t)b * Tn * 32;

    // trans column j packed in pairs
    ull tcp[16];
#pragma unroll
    for (int p = 0; p < 16; p++)
        tcp[p] = pack2(__ldg(trans + (2 * p) * Un + j),
                       __ldg(trans + (2 * p + 1) * Un + j));

    waitchunk(b, 0);
    float alpha = __ldg(lg + j);  // alpha0
    abuf[j] = alpha;              // parity 0
    __syncwarp();

    // 4-deep rotating logit prefetch
    float pl0 = ldclamp(lg, 1, tmax, j);
    float pl1 = ldclamp(lg, 2, tmax, j);
    float pl2 = ldclamp(lg, 3, tmax, j);
    float pl3 = ldclamp(lg, 4, tmax, j);

    int t = 1;
    for (; t + 3 <= tmax; t += 4) {
        if ((t & 63) == 1) waitchunk(b, (t >> 6) + 1);  // covers prefetch reach
        float n0 = ldclamp(lg, t + 4, tmax, j);
        float n1 = ldclamp(lg, t + 5, tmax, j);
        float n2 = ldclamp(lg, t + 6, tmax, j);
        float n3 = ldclamp(lg, t + 7, tmax, j);
        alpha = vstep32(t, pl0, tcp, abuf, gbp, j);
        alpha = vstep32(t + 1, pl1, tcp, abuf, gbp, j);
        alpha = vstep32(t + 2, pl2, tcp, abuf, gbp, j);
        alpha = vstep32(t + 3, pl3, tcp, abuf, gbp, j);
        pl0 = n0; pl1 = n1; pl2 = n2; pl3 = n3;
    }
    for (; t <= tmax; t++) {
        if ((t & 63) == 1) waitchunk(b, (t >> 6) + 1);
        alpha = vstep32(t, pl0, tcp, abuf, gbp, j);
        pl0 = pl1; pl1 = pl2; pl2 = pl3;
    }
    __syncwarp();
    __threadfence_block();  // order our STG.8 bp writes before warp re-reads them

    // final warp argmax, lowest-index tie-break
    float bv = alpha;
    int bi = j;
#pragma unroll
    for (int off = 16; off >= 1; off >>= 1) {
        float ov = __shfl_xor_sync(FULLM, bv, off);
        int oi = __shfl_xor_sync(FULLM, bi, off);
        if (ov > bv || (ov == bv && oi < bi)) { bv = ov; bi = oi; }
    }
    const int last_tag = bi;  // uniform after butterfly
    if (write_score && j == 0) out[score_off + b] = bv;

    if (write_pred) {
        // per-chunk backward maps from global bp: lane j = origin e, loop r = chunk
        int tg[32];
#pragma unroll
        for (int r = 0; r < 32; r++) tg[r] = j;
        for (int s = 0; s < 64; s++) {
#pragma unroll
            for (int r = 0; r < 32; r++) {
                int th = (r + 1) << 6;
                if (th > tmax) th = tmax;
                int tt = th - s;
                if (tt > (r << 6)) tg[r] = gbp[tt * 32 + tg[r]];
            }
        }
#pragma unroll
        for (int r = 0; r < 32; r++) pmap[r * 32 + j] = (unsigned char)tg[r];
        __syncwarp();

        const int cmax = tmax >> 6;
        if (j == 0) {
            int a = last_tag;
            for (int c = cmax; c >= 0; --c) {
                a = pmap[c * 32 + a];
                anch[c] = a;  // tag @ c*64
            }
        }
        // tail: pred[t] = last_tag for t >= tmax
        for (int tt = tmax + j; tt < Tn; tt += 32)
            out[(size_t)b * Tn + tt] = (float)last_tag;
        __syncwarp();

        // parallel per-chunk backtrack (lane c handles t in (c*64, t_hi])
        if (j <= cmax) {
            int thi2 = (j == cmax) ? tmax : ((j + 1) << 6);
            int tg2 = (j == cmax) ? last_tag : anch[j + 1];
            for (int tt = thi2; tt > (j << 6); --tt) {
                tg2 = gbp[tt * 32 + tg2];
                out[(size_t)b * Tn + tt - 1] = (float)tg2;
            }
        }
    }
}

// ================= persistent fused kernel with SM-role isolation ==============
__global__ __launch_bounds__(128, 3) void crf_fused(const float* __restrict__ x,
                                                    const int* __restrict__ nwords,
                                                    const float* __restrict__ W,
                                                    const float* __restrict__ trans,
                                                    const float* __restrict__ bias,
                                                    float* __restrict__ out,
                                                    int write_pred, int write_score,
                                                    long long score_off) {
    extern __shared__ char smem[];
    __shared__ int s_role;
    __shared__ int s_vb;
    __shared__ int s_job;

    const int tid = threadIdx.x;
    if (tid == 0) {
        unsigned smid;
        asm("mov.u32 %0, %%smid;" : "=r"(smid));
        int* rp = &g_ctrl[2048 + (smid & 255)];
        int r = atomicCAS(rp, 0, 1);
        if (r == 0) {  // first block on this SM
            int vb = atomicAdd(&g_ctrl[2304], 1);
            if (vb < NVIT) {
                s_vb = vb;
                atomicExch(rp, 3);
                s_role = 1;
            } else {
                atomicExch(rp, 2);
                s_role = 2;
            }
        } else {  // co-resident: wait for winner's decision
            volatile int* vp = rp;
            int v;
            while ((v = *vp) < 2) {}
            s_role = (v == 3) ? 0 : 2;  // leave viterbi SMs uncontended
        }
    }
    __syncthreads();
    const int role = s_role;
    if (role == 0) return;

    if (role == 1) {
        // 4 warps = 4 batches, one warp per SMSP, no cross-warp sync
        int w = tid >> 5;
        viterbi_warp(4 * s_vb + w, trans, out, write_pred, write_score, score_off,
                     nwords, smem + w * VWSTRIDE);
        return;
    }
    // gemm worker: pull chunk jobs (c-major -> chunk 0 of all batches first)
    while (true) {
        if (tid == 0) s_job = atomicAdd(&g_ctrl[2305], 1);
        __syncthreads();
        int job = s_job;
        if (job >= NJOBS) break;
        gemm_role(job >> 6, job & 63, x, W, bias, smem);
        __syncthreads();
    }
}

// ---------------- launch ----------------
extern "C" void kernel_launch(void* const* d_in, const int* in_sizes, int n_in,
                              void* d_out, int out_size) {
    const float* x = (const float*)d_in[0];
    const int* nwords = (const int*)d_in[1];
    const float* W = (const float*)d_in[2];
    const float* trans = (const float*)d_in[3];
    const float* bias = (const float*)d_in[4];
    float* out = (float*)d_out;

    const int BT = Bn * Tn;
    int write_pred = 1, write_score = 0;
    long long score_off = BT;
    if (out_size >= BT + Bn) {
        write_score = 1;
    } else if (out_size == Bn) {
        write_pred = 0;
        write_score = 1;
        score_off = 0;
    }

    static int* ctrl_ptr = nullptr;
    if (!ctrl_ptr) cudaGetSymbolAddress((void**)&ctrl_ptr, g_ctrl);

    cudaFuncSetAttribute(crf_fused, cudaFuncAttributeMaxDynamicSharedMemorySize, SMEM_BYTES);

    cudaMemsetAsync(ctrl_ptr, 0, (2048 + 256 + 2) * sizeof(int));
    crf_fused<<<NBLOCKS, 128, SMEM_BYTES>>>(x, nwords, W, trans, bias, out,
                                            write_pred, write_score, score_off);
}